// round 9
// baseline (speedup 1.0000x reference)
#include <cuda_runtime.h>
#include <cstdint>

#define NE    8192
#define DIM   128
#define PMAX  5
#define NNODE 512
#define TOTAL (NNODE * NNODE)

#define DOT_CTAS     256
#define DOT_THREADS  512
#define G_CTAS       128
#define THREADS      1024
#define PAIRS_CTA    (TOTAL / G_CTAS)          // 2048
#define TBL_BYTES    (PMAX * NE * 4)           // 163840
#define CHUNK_BYTES  (NE * 4)                  // 32768 (one p slice)
#define PATH_BYTES   (PAIRS_CTA * PMAX * 4)    // 40960
#define SMEM_BYTES   (TBL_BYTES + PATH_BYTES)  // 204800

// Precomputed dot products, layout [p][e].
__device__ float g_dots[PMAX * NE];
// Monotone counters (never reset -> graph-replay safe).
__device__ unsigned int g_done = 0;   // +DOT_CTAS per replay
__device__ unsigned int g_gen  = 0;   // +G_CTAS per replay

__device__ __forceinline__ uint32_t smem_u32(const void* p) {
    return (uint32_t)__cvta_generic_to_shared(p);
}

__device__ __forceinline__ void mbar_init(uint32_t mb) {
    asm volatile("mbarrier.init.shared.b64 [%0], 1;" :: "r"(mb));
}

__device__ __forceinline__ void mbar_wait(uint32_t mb) {
    uint32_t done;
    asm volatile(
        "{\n\t.reg .pred p;\n\t"
        "mbarrier.try_wait.parity.acquire.cta.shared::cta.b64 p, [%1], 0;\n\t"
        "selp.b32 %0, 1, 0, p;\n\t}"
        : "=r"(done) : "r"(mb) : "memory");
    while (!done) {
        asm volatile(
            "{\n\t.reg .pred p;\n\t"
            "mbarrier.try_wait.parity.acquire.cta.shared::cta.b64 p, [%1], 0, 0x989680;\n\t"
            "selp.b32 %0, 1, 0, p;\n\t}"
            : "=r"(done) : "r"(mb) : "memory");
    }
}

__device__ __forceinline__ void bulk_copy(uint32_t dst, const void* src,
                                          uint32_t bytes, uint32_t mb) {
    asm volatile(
        "cp.async.bulk.shared::cta.global.mbarrier::complete_tx::bytes "
        "[%0], [%1], %2, [%3];"
        :: "r"(dst), "l"(src), "r"(bytes), "r"(mb) : "memory");
}

// ---------------------------------------------------------------------------
// Kernel 1 (PDL primary): dots[p][e] = sum_d emb[e][d] * ev[p][d]
// 256 CTAs x 512 threads (single wave, co-residency-friendly regs), warp -> 2
// edges. Triggers dependent launch at entry; signals completion via g_done.
// ---------------------------------------------------------------------------
__global__ __launch_bounds__(DOT_THREADS) void edge_dot_kernel(
        const float* __restrict__ emb, const float* __restrict__ ev) {
    // Allow the gather kernel to launch immediately.
    asm volatile("griddepcontrol.launch_dependents;" ::: "memory");

    const int lane = threadIdx.x & 31;
    const int w    = threadIdx.x >> 5;                  // 0..15
    const int e0   = (blockIdx.x * 16 + w) * 2;

    float4 a0 = __ldg(((const float4*)emb) + (e0    ) * (DIM / 4) + lane);
    float4 a1 = __ldg(((const float4*)emb) + (e0 + 1) * (DIM / 4) + lane);

    float4 evr[PMAX];
#pragma unroll
    for (int p = 0; p < PMAX; ++p)
        evr[p] = __ldg(((const float4*)ev) + p * (DIM / 4) + lane);

    float pa[PMAX], pb[PMAX];
#pragma unroll
    for (int p = 0; p < PMAX; ++p) {
        pa[p] = a0.x * evr[p].x + a0.y * evr[p].y + a0.z * evr[p].z + a0.w * evr[p].w;
        pb[p] = a1.x * evr[p].x + a1.y * evr[p].y + a1.z * evr[p].z + a1.w * evr[p].w;
    }
#pragma unroll
    for (int off = 16; off > 0; off >>= 1) {
#pragma unroll
        for (int p = 0; p < PMAX; ++p) {
            pa[p] += __shfl_xor_sync(0xffffffffu, pa[p], off);
            pb[p] += __shfl_xor_sync(0xffffffffu, pb[p], off);
        }
    }
    if (lane == 0) {
#pragma unroll
        for (int p = 0; p < PMAX; ++p) {
            g_dots[p * NE + e0]     = pa[p];
            g_dots[p * NE + e0 + 1] = pb[p];
        }
        __threadfence();               // flush this warp's STGs GPU-wide
    }
    __syncthreads();
    if (threadIdx.x == 0)
        atomicAdd(&g_done, 1u);        // CTA done (after fences)
}

// ---------------------------------------------------------------------------
// Kernel 2 (PDL secondary): 128 CTAs x 1024 threads x 2 pairs = 262144.
// Launches while kernel 1 runs. Prologue (paths copy + index reads) is
// independent of g_dots; table chunks are issued only after the generation
// spin confirms all dot CTAs finished.
// ---------------------------------------------------------------------------
__global__ __launch_bounds__(THREADS, 1) void gather_kernel(
        const int* __restrict__ paths, float* __restrict__ out) {
    extern __shared__ __align__(16) char smem[];
    float* s_dots  = (float*)smem;                 // 163840 B
    int*   s_paths = (int*)(smem + TBL_BYTES);     // 40960 B
    __shared__ __align__(8) unsigned long long mbars[6]; // [0..4]=chunks, 5=paths

    const int tid = threadIdx.x;
    uint32_t mbc[PMAX];
#pragma unroll
    for (int p = 0; p < PMAX; ++p) mbc[p] = smem_u32(&mbars[p]);
    const uint32_t mbp = smem_u32(&mbars[5]);

    if (tid == 0) {
#pragma unroll
        for (int i = 0; i < 6; ++i) mbar_init(smem_u32(&mbars[i]));
    }
    __syncthreads();

    if (tid == 0) {
        // paths slice: independent of dots -> overlaps the dot kernel
        asm volatile("mbarrier.arrive.expect_tx.shared.b64 _, [%0], %1;"
                     :: "r"(mbp), "r"((uint32_t)PATH_BYTES) : "memory");
        bulk_copy(smem_u32(s_paths),
                  (const char*)paths + blockIdx.x * PATH_BYTES,
                  PATH_BYTES, mbp);

        // wait for the dot kernel (monotone generation counter)
        unsigned int t = atomicAdd(&g_gen, 1u);
        unsigned int target = (t / G_CTAS + 1u) * DOT_CTAS;
        volatile unsigned int* vd = &g_done;
        while (*vd < target) { }
        __threadfence();                                   // acquire
        asm volatile("fence.proxy.async.global;" ::: "memory");

        // dots table: one chunk per p
#pragma unroll
        for (int p = 0; p < PMAX; ++p) {
            asm volatile("mbarrier.arrive.expect_tx.shared.b64 _, [%0], %1;"
                         :: "r"(mbc[p]), "r"((uint32_t)CHUNK_BYTES) : "memory");
            bulk_copy(smem_u32(s_dots) + p * CHUNK_BYTES,
                      (const char*)g_dots + p * CHUNK_BYTES,
                      CHUNK_BYTES, mbc[p]);
        }
    }

    // --- indices: thread t -> pairs t and t+1024; stride-5 = conflict-free
    mbar_wait(mbp);
    int e0[PMAX], e1[PMAX];
#pragma unroll
    for (int p = 0; p < PMAX; ++p) e0[p] = s_paths[5 * tid + p];
#pragma unroll
    for (int p = 0; p < PMAX; ++p) e1[p] = s_paths[5 * (tid + 1024) + p];

    int c0 = 0, c1 = 0;
#pragma unroll
    for (int p = 0; p < PMAX; ++p) { if (e0[p] >= 0) ++c0; if (e1[p] >= 0) ++c1; }

    // --- chunked gather: consume each p-slice as it lands
    float a0 = 0.f, a1 = 0.f;
#pragma unroll
    for (int p = 0; p < PMAX; ++p) {
        mbar_wait(mbc[p]);
        const float* tp = s_dots + p * NE;
        if (e0[p] >= 0) a0 += tp[e0[p]];
        if (e1[p] >= 0) a1 += tp[e1[p]];
    }

    float* ob = out + blockIdx.x * PAIRS_CTA;
    ob[tid]        = c0 ? a0 / (float)c0 : 0.0f;
    ob[tid + 1024] = c1 ? a1 / (float)c1 : 0.0f;
}

// ---------------------------------------------------------------------------
// Launch: primary normally, secondary with programmatic stream serialization.
// ---------------------------------------------------------------------------
extern "C" void kernel_launch(void* const* d_in, const int* in_sizes, int n_in,
                              void* d_out, int out_size) {
    const float* emb   = nullptr;
    const int*   paths = nullptr;
    const float* ev    = nullptr;
    for (int i = 0; i < n_in; ++i) {
        if (in_sizes[i] == NE * DIM)                  emb   = (const float*)d_in[i];
        else if (in_sizes[i] == NNODE * NNODE * PMAX) paths = (const int*)d_in[i];
        else if (in_sizes[i] == PMAX * DIM)           ev    = (const float*)d_in[i];
    }
    float* out = (float*)d_out;

    edge_dot_kernel<<<DOT_CTAS, DOT_THREADS>>>(emb, ev);

    cudaFuncSetAttribute(gather_kernel,
                         cudaFuncAttributeMaxDynamicSharedMemorySize,
                         SMEM_BYTES);

    cudaLaunchConfig_t cfg = {};
    cfg.gridDim         = dim3(G_CTAS, 1, 1);
    cfg.blockDim        = dim3(THREADS, 1, 1);
    cfg.dynamicSmemBytes = SMEM_BYTES;
    cudaLaunchAttribute attr[1];
    attr[0].id = cudaLaunchAttributeProgrammaticStreamSerialization;
    attr[0].val.programmaticStreamSerializationAllowed = 1;
    cfg.attrs    = attr;
    cfg.numAttrs = 1;
    cudaLaunchKernelEx(&cfg, gather_kernel, paths, out);
}

// round 10
// speedup vs baseline: 1.1875x; 1.1875x over previous
#include <cuda_runtime.h>
#include <cstdint>

#define NE    8192
#define DIM   128
#define PMAX  5
#define NNODE 512
#define TOTAL (NNODE * NNODE)

#define DOT_CTAS     256
#define DOT_THREADS  256
#define G_CTAS       128
#define THREADS      1024
#define PAIRS_CTA    (TOTAL / G_CTAS)          // 2048
#define TBL_BYTES    (PMAX * NE * 4)           // 163840
#define CHUNK_BYTES  (NE * 4)                  // 32768 (one p slice)
#define PATH_BYTES   (PAIRS_CTA * PMAX * 4)    // 40960
#define SMEM_BYTES   (TBL_BYTES + PATH_BYTES)  // 204800

// Precomputed dot products, layout [p][e].
__device__ float g_dots[PMAX * NE];
// Monotone counters (never reset -> graph-replay safe).
__device__ unsigned int g_done = 0;   // +DOT_CTAS per replay
__device__ unsigned int g_gen  = 0;   // +G_CTAS  per replay

__device__ __forceinline__ uint32_t smem_u32(const void* p) {
    return (uint32_t)__cvta_generic_to_shared(p);
}

__device__ __forceinline__ void mbar_init(uint32_t mb) {
    asm volatile("mbarrier.init.shared.b64 [%0], 1;" :: "r"(mb));
}

__device__ __forceinline__ void mbar_wait(uint32_t mb) {
    uint32_t done;
    asm volatile(
        "{\n\t.reg .pred p;\n\t"
        "mbarrier.try_wait.parity.acquire.cta.shared::cta.b64 p, [%1], 0;\n\t"
        "selp.b32 %0, 1, 0, p;\n\t}"
        : "=r"(done) : "r"(mb) : "memory");
    while (!done) {
        asm volatile(
            "{\n\t.reg .pred p;\n\t"
            "mbarrier.try_wait.parity.acquire.cta.shared::cta.b64 p, [%1], 0, 0x989680;\n\t"
            "selp.b32 %0, 1, 0, p;\n\t}"
            : "=r"(done) : "r"(mb) : "memory");
    }
}

__device__ __forceinline__ void bulk_copy(uint32_t dst, const void* src,
                                          uint32_t bytes, uint32_t mb) {
    asm volatile(
        "cp.async.bulk.shared::cta.global.mbarrier::complete_tx::bytes "
        "[%0], [%1], %2, [%3];"
        :: "r"(dst), "l"(src), "r"(bytes), "r"(mb) : "memory");
}

// ---------------------------------------------------------------------------
// Kernel 1 (PDL primary): dots[p][e] = sum_d emb[e][d] * ev[p][d]
// 256 CTAs x 256 threads = SINGLE WAVE -> launch_dependents fires early.
// Warp handles 4 edges in two groups of 2 (bounded registers).
// ---------------------------------------------------------------------------
__global__ __launch_bounds__(DOT_THREADS, 2) void edge_dot_kernel(
        const float* __restrict__ emb, const float* __restrict__ ev) {
    asm volatile("griddepcontrol.launch_dependents;" ::: "memory");

    const int lane = threadIdx.x & 31;
    const int w    = threadIdx.x >> 5;                 // 0..7
    const int eb   = (blockIdx.x * 8 + w) * 4;         // 4 edges per warp

    float4 evr[PMAX];
#pragma unroll
    for (int p = 0; p < PMAX; ++p)
        evr[p] = __ldg(((const float4*)ev) + p * (DIM / 4) + lane);

#pragma unroll
    for (int g = 0; g < 2; ++g) {
        const int e0 = eb + g * 2;
        float4 a0 = __ldg(((const float4*)emb) + (e0    ) * (DIM / 4) + lane);
        float4 a1 = __ldg(((const float4*)emb) + (e0 + 1) * (DIM / 4) + lane);

        float pa[PMAX], pb[PMAX];
#pragma unroll
        for (int p = 0; p < PMAX; ++p) {
            pa[p] = a0.x * evr[p].x + a0.y * evr[p].y + a0.z * evr[p].z + a0.w * evr[p].w;
            pb[p] = a1.x * evr[p].x + a1.y * evr[p].y + a1.z * evr[p].z + a1.w * evr[p].w;
        }
#pragma unroll
        for (int off = 16; off > 0; off >>= 1) {
#pragma unroll
            for (int p = 0; p < PMAX; ++p) {
                pa[p] += __shfl_xor_sync(0xffffffffu, pa[p], off);
                pb[p] += __shfl_xor_sync(0xffffffffu, pb[p], off);
            }
        }
        if (lane == 0) {
#pragma unroll
            for (int p = 0; p < PMAX; ++p) {
                g_dots[p * NE + e0]     = pa[p];
                g_dots[p * NE + e0 + 1] = pb[p];
            }
        }
    }

    if (lane == 0) __threadfence();        // flush this warp's STGs GPU-wide
    __syncthreads();
    if (threadIdx.x == 0)
        atomicAdd(&g_done, 1u);            // CTA done (after all fences)
}

// ---------------------------------------------------------------------------
// Kernel 2 (PDL secondary): 128 CTAs x 1024 threads x 2 pairs = 262144.
// R8 gather verbatim; tid0 additionally spins on the monotone done-counter
// before issuing the table chunks. Paths copy + index reads overlap the dot
// kernel; worst case (no overlap) degenerates to exactly R8 behavior.
// ---------------------------------------------------------------------------
__global__ __launch_bounds__(THREADS, 1) void gather_kernel(
        const int* __restrict__ paths, float* __restrict__ out) {
    extern __shared__ __align__(16) char smem[];
    float* s_dots  = (float*)smem;                 // 163840 B
    int*   s_paths = (int*)(smem + TBL_BYTES);     // 40960 B
    __shared__ __align__(8) unsigned long long mbars[6]; // [0..4]=chunks, 5=paths

    const int tid = threadIdx.x;
    uint32_t mbc[PMAX];
#pragma unroll
    for (int p = 0; p < PMAX; ++p) mbc[p] = smem_u32(&mbars[p]);
    const uint32_t mbp = smem_u32(&mbars[5]);

    if (tid == 0) {
#pragma unroll
        for (int i = 0; i < 6; ++i) mbar_init(smem_u32(&mbars[i]));
        asm volatile("fence.proxy.async.shared::cta;" ::: "memory");
        // paths slice: independent of dots -> overlaps the dot kernel
        asm volatile("mbarrier.arrive.expect_tx.shared.b64 _, [%0], %1;"
                     :: "r"(mbp), "r"((uint32_t)PATH_BYTES) : "memory");
        bulk_copy(smem_u32(s_paths),
                  (const char*)paths + blockIdx.x * PATH_BYTES,
                  PATH_BYTES, mbp);
    }
    __syncthreads();

    if (tid == 0) {
        // wait for the dot kernel (monotone generation counter)
        unsigned int t = atomicAdd(&g_gen, 1u);
        unsigned int target = (t / G_CTAS + 1u) * DOT_CTAS;
        volatile unsigned int* vd = &g_done;
        while (*vd < target) { }
        __threadfence();                                   // acquire
        asm volatile("fence.proxy.async.global;" ::: "memory");

        // dots table: one chunk per p
#pragma unroll
        for (int p = 0; p < PMAX; ++p) {
            asm volatile("mbarrier.arrive.expect_tx.shared.b64 _, [%0], %1;"
                         :: "r"(mbc[p]), "r"((uint32_t)CHUNK_BYTES) : "memory");
            bulk_copy(smem_u32(s_dots) + p * CHUNK_BYTES,
                      (const char*)g_dots + p * CHUNK_BYTES,
                      CHUNK_BYTES, mbc[p]);
        }
    }

    // --- indices: thread t -> pairs t and t+1024; stride-5 = conflict-free
    //     (runs during tid0's spin: overlaps the dot kernel)
    mbar_wait(mbp);
    int e0[PMAX], e1[PMAX];
#pragma unroll
    for (int p = 0; p < PMAX; ++p) e0[p] = s_paths[5 * tid + p];
#pragma unroll
    for (int p = 0; p < PMAX; ++p) e1[p] = s_paths[5 * (tid + 1024) + p];

    int c0 = 0, c1 = 0;
#pragma unroll
    for (int p = 0; p < PMAX; ++p) { if (e0[p] >= 0) ++c0; if (e1[p] >= 0) ++c1; }

    // --- chunked gather: consume each p-slice as it lands
    float a0 = 0.f, a1 = 0.f;
#pragma unroll
    for (int p = 0; p < PMAX; ++p) {
        mbar_wait(mbc[p]);
        const float* tp = s_dots + p * NE;
        if (e0[p] >= 0) a0 += tp[e0[p]];
        if (e1[p] >= 0) a1 += tp[e1[p]];
    }

    float* ob = out + blockIdx.x * PAIRS_CTA;
    ob[tid]        = c0 ? a0 / (float)c0 : 0.0f;
    ob[tid + 1024] = c1 ? a1 / (float)c1 : 0.0f;
}

// ---------------------------------------------------------------------------
// Launch: primary (carveout-matched) + secondary with programmatic
// stream serialization.
// ---------------------------------------------------------------------------
extern "C" void kernel_launch(void* const* d_in, const int* in_sizes, int n_in,
                              void* d_out, int out_size) {
    const float* emb   = nullptr;
    const int*   paths = nullptr;
    const float* ev    = nullptr;
    for (int i = 0; i < n_in; ++i) {
        if (in_sizes[i] == NE * DIM)                  emb   = (const float*)d_in[i];
        else if (in_sizes[i] == NNODE * NNODE * PMAX) paths = (const int*)d_in[i];
        else if (in_sizes[i] == PMAX * DIM)           ev    = (const float*)d_in[i];
    }
    float* out = (float*)d_out;

    // Match the gather kernel's max-smem carveout to avoid per-SM L1
    // reconfiguration stalls when gather CTAs co-schedule with dot CTAs.
    cudaFuncSetAttribute(edge_dot_kernel,
                         cudaFuncAttributePreferredSharedMemoryCarveout, 100);
    cudaFuncSetAttribute(gather_kernel,
                         cudaFuncAttributeMaxDynamicSharedMemorySize,
                         SMEM_BYTES);

    edge_dot_kernel<<<DOT_CTAS, DOT_THREADS>>>(emb, ev);

    cudaLaunchConfig_t cfg = {};
    cfg.gridDim          = dim3(G_CTAS, 1, 1);
    cfg.blockDim         = dim3(THREADS, 1, 1);
    cfg.dynamicSmemBytes = SMEM_BYTES;
    cudaLaunchAttribute attr[1];
    attr[0].id = cudaLaunchAttributeProgrammaticStreamSerialization;
    attr[0].val.programmaticStreamSerializationAllowed = 1;
    cfg.attrs    = attr;
    cfg.numAttrs = 1;
    cudaLaunchKernelEx(&cfg, gather_kernel, paths, out);
}